// round 1
// baseline (speedup 1.0000x reference)
#include <cuda_runtime.h>

// bg: (1, 4, 32, 32, 32, 16) f32   -> d_in[0]
// gm: (1, 1, 128, 128, 128) f32    -> d_in[1]
// out:(1, 4, 128, 128, 128) f32

#define GH 128
#define GWD 128
#define GD 128
#define H 32
#define W 32
#define D 32
#define UP 16
#define NC 4
#define TH 4           // gh tile
#define TW 4           // gw tile
#define NROW 9         // 3 x-cells * 3 y-cells
#define ROWF4 (D*UP)   // 512 float4 per (x,y) row: [z][t] with channels packed in float4
#define SMEM_F4 (NROW*ROWF4)           // 4608 float4
#define SMEM_BYTES (SMEM_F4 * 16)      // 73728 B

#define CH_STRIDE (H*W*D*UP)           // 524288 floats between bg channels
#define OUT_CH (GH*GWD*GD)             // 2097152 floats between out channels

__global__ void __launch_bounds__(256)
bgrid_slice_kernel(const float* __restrict__ bg,
                   const float* __restrict__ gm,
                   float* __restrict__ out)
{
    extern __shared__ float4 S[];   // S[row][z][t] = float4 over 4 channels

    const float sx = 31.0f / 127.0f;   // (size-1)/(gsize-1), same for x,y,z

    const int gh0 = blockIdx.y * TH;
    const int gw0 = blockIdx.x * TW;
    const int X = (int)floorf((float)gh0 * sx);
    const int Y = (int)floorf((float)gw0 * sx);
    const int tid = threadIdx.x;

    // ---- Stage 9 corner rows into shared, transposing channels into float4 ----
    // bg index: ((c*H + x)*W + y)*(D*UP) + z*UP + t
    #pragma unroll
    for (int p = tid; p < SMEM_F4; p += 256) {
        int row = p >> 9;          // p / 512
        int zt  = p & 511;
        int lx = row / 3;
        int ly = row - lx * 3;
        int gx = min(X + lx, H - 1);
        int gy = min(Y + ly, W - 1);
        int base = (gx * W + gy) * (D * UP) + zt;
        float4 v;
        v.x = bg[base];
        v.y = bg[base + CH_STRIDE];
        v.z = bg[base + 2 * CH_STRIDE];
        v.w = bg[base + 3 * CH_STRIDE];
        S[p] = v;
    }
    __syncthreads();

    // ---- Slice: 4x4 columns x 128 depth = 2048 voxels, 8 per thread ----
    #pragma unroll
    for (int k = 0; k < (TH * TW * GD) / 256; k++) {
        int v  = k * 256 + tid;
        int gd = v & (GD - 1);
        int col = v >> 7;           // 0..15, uniform per warp
        int lh = col >> 2;
        int lw = col & 3;
        int gh = gh0 + lh;
        int gw = gw0 + lw;

        // x coordinate (per column, uniform within warp)
        float xc = fminf((float)gh * sx, 31.0f);
        float x0f = floorf(xc);
        float fx = xc - x0f;
        int x0 = (int)x0f;
        int x1 = min(x0 + 1, H - 1);
        int lx0 = x0 - X, lx1 = x1 - X;

        float yc = fminf((float)gw * sx, 31.0f);
        float y0f = floorf(yc);
        float fy = yc - y0f;
        int y0 = (int)y0f;
        int y1 = min(y0 + 1, W - 1);
        int ly0 = y0 - Y, ly1 = y1 - Y;

        float zc = fminf((float)gd * sx, 31.0f);
        float z0f = floorf(zc);
        float fz = zc - z0f;
        int z0 = (int)z0f;
        int z1 = min(z0 + 1, D - 1);

        float g = gm[(gh * GWD + gw) * GD + gd];
        float t = fminf(fmaxf(g * 15.0f, 0.0f), 15.0f);
        float t0f = floorf(t);
        float ft = t - t0f;
        int t0 = (int)t0f;
        int t1 = min(t0 + 1, UP - 1);

        float wt0 = 1.0f - ft, wt1 = ft;
        float wx0 = 1.0f - fx, wx1 = fx;
        float wy0 = 1.0f - fy, wy1 = fy;
        float wz0 = 1.0f - fz, wz1 = fz;

        int rows[4];
        rows[0] = (lx0 * 3 + ly0) * ROWF4;
        rows[1] = (lx0 * 3 + ly1) * ROWF4;
        rows[2] = (lx1 * 3 + ly0) * ROWF4;
        rows[3] = (lx1 * 3 + ly1) * ROWF4;
        float wxy[4];
        wxy[0] = wx0 * wy0;
        wxy[1] = wx0 * wy1;
        wxy[2] = wx1 * wy0;
        wxy[3] = wx1 * wy1;
        int zoff[2] = { z0 * UP, z1 * UP };
        float wzz[2] = { wz0, wz1 };

        float4 acc = make_float4(0.f, 0.f, 0.f, 0.f);

        #pragma unroll
        for (int cidx = 0; cidx < 4; cidx++) {
            #pragma unroll
            for (int kz = 0; kz < 2; kz++) {
                int base = rows[cidx] + zoff[kz];
                float4 a = S[base + t0];
                float4 b = S[base + t1];
                float wsp = wxy[cidx] * wzz[kz];
                float wa = wsp * wt0;
                float wb = wsp * wt1;
                acc.x = fmaf(a.x, wa, acc.x);
                acc.y = fmaf(a.y, wa, acc.y);
                acc.z = fmaf(a.z, wa, acc.z);
                acc.w = fmaf(a.w, wa, acc.w);
                acc.x = fmaf(b.x, wb, acc.x);
                acc.y = fmaf(b.y, wb, acc.y);
                acc.z = fmaf(b.z, wb, acc.z);
                acc.w = fmaf(b.w, wb, acc.w);
            }
        }

        int ob = (gh * GWD + gw) * GD + gd;
        out[ob]               = acc.x;
        out[ob + OUT_CH]      = acc.y;
        out[ob + 2 * OUT_CH]  = acc.z;
        out[ob + 3 * OUT_CH]  = acc.w;
    }
}

extern "C" void kernel_launch(void* const* d_in, const int* in_sizes, int n_in,
                              void* d_out, int out_size)
{
    const float* bg = (const float*)d_in[0];
    const float* gm = (const float*)d_in[1];
    float* out = (float*)d_out;

    // 73728 B dynamic smem exceeds the 48KB default; raise the limit (idempotent,
    // not a stream op — safe under graph capture).
    cudaFuncSetAttribute(bgrid_slice_kernel,
                         cudaFuncAttributeMaxDynamicSharedMemorySize, SMEM_BYTES);

    dim3 grid(GWD / TW, GH / TH);   // 32 x 32 = 1024 blocks
    bgrid_slice_kernel<<<grid, 256, SMEM_BYTES>>>(bg, gm, out);
}

// round 2
// speedup vs baseline: 1.5301x; 1.5301x over previous
#include <cuda_runtime.h>
#include <cuda_fp16.h>

// bg: (1, 4, 32, 32, 32, 16) f32   -> d_in[0]
// gm: (1, 1, 128, 128, 128) f32    -> d_in[1]
// out:(1, 4, 128, 128, 128) f32

#define GH 128
#define GWD 128
#define GD 128
#define H 32
#define W 32
#define D 32
#define UP 16
#define TH 4           // gh tile
#define TW 4           // gw tile
#define NROW 9         // 3 x-cells * 3 y-cells
#define ROWE (D*UP)    // 512 entries per (x,y) row: [z][t], 4 channels packed fp16 (8B)
#define SMEM_E (NROW*ROWE)             // 4608 uint2
#define SMEM_BYTES (SMEM_E * 8)        // 36864 B

#define CH_STRIDE (H*W*D*UP)           // 524288 floats between bg channels
#define OUT_CH (GH*GWD*GD)             // 2097152 floats between out channels

__global__ void __launch_bounds__(256)
bgrid_slice_kernel(const float* __restrict__ bg,
                   const float* __restrict__ gm,
                   float* __restrict__ out)
{
    extern __shared__ uint2 S[];   // S[row][z][t] = {half2(c0,c1), half2(c2,c3)}

    const float sx = 31.0f / 127.0f;   // (size-1)/(gsize-1), same for x,y,z

    const int gh0 = blockIdx.y * TH;
    const int gw0 = blockIdx.x * TW;
    const int X = (int)floorf((float)gh0 * sx);
    const int Y = (int)floorf((float)gw0 * sx);
    const int tid = threadIdx.x;

    // ---- Stage 9 corner rows into shared as fp16x4, channels packed ----
    // bg index: ((c*H + x)*W + y)*(D*UP) + z*UP + t
    #pragma unroll
    for (int p = tid; p < SMEM_E; p += 256) {
        int row = p >> 9;          // p / 512
        int zt  = p & 511;
        int lx = row / 3;
        int ly = row - lx * 3;
        int gx = min(X + lx, H - 1);
        int gy = min(Y + ly, W - 1);
        int base = (gx * W + gy) * (D * UP) + zt;
        __half2 h01 = __floats2half2_rn(bg[base],               bg[base + CH_STRIDE]);
        __half2 h23 = __floats2half2_rn(bg[base + 2*CH_STRIDE], bg[base + 3*CH_STRIDE]);
        uint2 v;
        v.x = *reinterpret_cast<unsigned int*>(&h01);
        v.y = *reinterpret_cast<unsigned int*>(&h23);
        S[p] = v;
    }
    __syncthreads();

    // ---- Slice: 4x4 columns x 128 depth = 2048 voxels, 8 per thread ----
    #pragma unroll
    for (int k = 0; k < (TH * TW * GD) / 256; k++) {
        int v  = k * 256 + tid;
        int gd = v & (GD - 1);
        int col = v >> 7;           // 0..15, uniform per warp
        int lh = col >> 2;
        int lw = col & 3;
        int gh = gh0 + lh;
        int gw = gw0 + lw;

        float xc = fminf((float)gh * sx, 31.0f);
        float x0f = floorf(xc);
        float fx = xc - x0f;
        int x0 = (int)x0f;
        int x1 = min(x0 + 1, H - 1);
        int lx0 = x0 - X, lx1 = x1 - X;

        float yc = fminf((float)gw * sx, 31.0f);
        float y0f = floorf(yc);
        float fy = yc - y0f;
        int y0 = (int)y0f;
        int y1 = min(y0 + 1, W - 1);
        int ly0 = y0 - Y, ly1 = y1 - Y;

        float zc = fminf((float)gd * sx, 31.0f);
        float z0f = floorf(zc);
        float fz = zc - z0f;
        int z0 = (int)z0f;
        int z1 = min(z0 + 1, D - 1);

        float g = gm[(gh * GWD + gw) * GD + gd];
        float t = fminf(fmaxf(g * 15.0f, 0.0f), 15.0f);
        float t0f = floorf(t);
        float ft = t - t0f;
        int t0 = (int)t0f;
        int t1 = min(t0 + 1, UP - 1);

        float wt0 = 1.0f - ft, wt1 = ft;
        float wx0 = 1.0f - fx, wx1 = fx;
        float wy0 = 1.0f - fy, wy1 = fy;
        float wz0 = 1.0f - fz, wz1 = fz;

        int rows[4];
        rows[0] = (lx0 * 3 + ly0) * ROWE;
        rows[1] = (lx0 * 3 + ly1) * ROWE;
        rows[2] = (lx1 * 3 + ly0) * ROWE;
        rows[3] = (lx1 * 3 + ly1) * ROWE;
        float wxy[4];
        wxy[0] = wx0 * wy0;
        wxy[1] = wx0 * wy1;
        wxy[2] = wx1 * wy0;
        wxy[3] = wx1 * wy1;
        int zoff[2] = { z0 * UP, z1 * UP };
        float wzz[2] = { wz0, wz1 };

        float acc0 = 0.f, acc1 = 0.f, acc2 = 0.f, acc3 = 0.f;

        #pragma unroll
        for (int cidx = 0; cidx < 4; cidx++) {
            #pragma unroll
            for (int kz = 0; kz < 2; kz++) {
                int base = rows[cidx] + zoff[kz];
                uint2 ua = S[base + t0];
                uint2 ub = S[base + t1];
                float wsp = wxy[cidx] * wzz[kz];
                float wa = wsp * wt0;
                float wb = wsp * wt1;
                float2 a01 = __half22float2(*reinterpret_cast<__half2*>(&ua.x));
                float2 a23 = __half22float2(*reinterpret_cast<__half2*>(&ua.y));
                float2 b01 = __half22float2(*reinterpret_cast<__half2*>(&ub.x));
                float2 b23 = __half22float2(*reinterpret_cast<__half2*>(&ub.y));
                acc0 = fmaf(a01.x, wa, acc0);
                acc1 = fmaf(a01.y, wa, acc1);
                acc2 = fmaf(a23.x, wa, acc2);
                acc3 = fmaf(a23.y, wa, acc3);
                acc0 = fmaf(b01.x, wb, acc0);
                acc1 = fmaf(b01.y, wb, acc1);
                acc2 = fmaf(b23.x, wb, acc2);
                acc3 = fmaf(b23.y, wb, acc3);
            }
        }

        int ob = (gh * GWD + gw) * GD + gd;
        out[ob]               = acc0;
        out[ob + OUT_CH]      = acc1;
        out[ob + 2 * OUT_CH]  = acc2;
        out[ob + 3 * OUT_CH]  = acc3;
    }
}

extern "C" void kernel_launch(void* const* d_in, const int* in_sizes, int n_in,
                              void* d_out, int out_size)
{
    const float* bg = (const float*)d_in[0];
    const float* gm = (const float*)d_in[1];
    float* out = (float*)d_out;

    dim3 grid(GWD / TW, GH / TH);   // 32 x 32 = 1024 blocks
    bgrid_slice_kernel<<<grid, 256, SMEM_BYTES>>>(bg, gm, out);
}

// round 3
// speedup vs baseline: 1.6447x; 1.0749x over previous
#include <cuda_runtime.h>
#include <cuda_fp16.h>

// bg: (1, 4, 32, 32, 32, 16) f32   -> d_in[0]
// gm: (1, 1, 128, 128, 128) f32    -> d_in[1]
// out:(1, 4, 128, 128, 128) f32

#define GH 128
#define GWD 128
#define GD 128
#define H 32
#define W 32
#define D 32
#define UP 16
#define TH 4
#define TW 4
#define ROWE 512            // entries per (x,y) row: [z][t], fp16x4 (8B each)
#define SROWS_E 4608        // 9 rows * 512
#define PLANE_E 4096        // 8 columns * 512
#define SROWS_BYTES (SROWS_E * 8)   // 36864
#define PLANE_BYTES (PLANE_E * 8)   // 32768
#define SMEM_BYTES (SROWS_BYTES + PLANE_BYTES + 256 + 64)

#define CH_STRIDE (H*W*D*UP)        // 524288
#define OUT_CH (GH*GWD*GD)          // 2097152

__device__ __forceinline__ __half2 u2h(unsigned int u) {
    __half2 h; *reinterpret_cast<unsigned int*>(&h) = u; return h;
}
__device__ __forceinline__ unsigned int h2u(__half2 h) {
    return *reinterpret_cast<unsigned int*>(&h);
}

__global__ void __launch_bounds__(256, 3)
bgrid_slice_kernel(const float* __restrict__ bg,
                   const float* __restrict__ gm,
                   float* __restrict__ out)
{
    extern __shared__ char smem[];
    uint2* S_rows  = reinterpret_cast<uint2*>(smem);
    uint2* S_plane = reinterpret_cast<uint2*>(smem + SROWS_BYTES);
    uint4* CW      = reinterpret_cast<uint4*>(smem + SROWS_BYTES + PLANE_BYTES);
    int*   CB      = reinterpret_cast<int*>  (smem + SROWS_BYTES + PLANE_BYTES + 256);

    const float sx = 31.0f / 127.0f;
    const int gh0 = blockIdx.y * TH;
    const int gw0 = blockIdx.x * TW;
    const int X = (int)floorf((float)gh0 * sx);
    const int Y = (int)floorf((float)gw0 * sx);
    const int tid = threadIdx.x;

    // ---- phase 1: stage 9 corner rows as fp16x4 (channels packed) ----
    #pragma unroll
    for (int p = tid; p < SROWS_E; p += 256) {
        int row = p >> 9;
        int zt  = p & 511;
        int lx = row / 3;
        int ly = row - lx * 3;
        int gx = min(X + lx, H - 1);
        int gy = min(Y + ly, W - 1);
        int base = (gx * W + gy) * ROWE + zt;
        __half2 h01 = __floats2half2_rn(bg[base],               bg[base + CH_STRIDE]);
        __half2 h23 = __floats2half2_rn(bg[base + 2*CH_STRIDE], bg[base + 3*CH_STRIDE]);
        uint2 v; v.x = h2u(h01); v.y = h2u(h23);
        S_rows[p] = v;
    }

    // ---- phase 1b: per-column xy weights (half2) + base-row offsets ----
    if (tid < 16) {
        int lh = tid >> 2, lw = tid & 3;
        float xc = fminf((float)(gh0 + lh) * sx, 31.0f);
        float x0f = floorf(xc); float fx = xc - x0f;
        int lx0 = (int)x0f - X;
        float yc = fminf((float)(gw0 + lw) * sx, 31.0f);
        float y0f = floorf(yc); float fy = yc - y0f;
        int ly0 = (int)y0f - Y;
        uint4 w;
        w.x = h2u(__float2half2_rn((1.f - fx) * (1.f - fy)));
        w.y = h2u(__float2half2_rn((1.f - fx) * fy));
        w.z = h2u(__float2half2_rn(fx * (1.f - fy)));
        w.w = h2u(__float2half2_rn(fx * fy));
        CW[tid] = w;
        CB[tid] = (lx0 * 3 + ly0) * ROWE;   // rows needed: b00, +512, +1536, +2048 (max idx 4607)
    }
    __syncthreads();

    #pragma unroll
    for (int h = 0; h < 2; h++) {
        // ---- phase 2: blend 8 column planes (fp16, HFMA2) ----
        const int zt0 = tid * 2;
        #pragma unroll
        for (int i = 0; i < 8; i++) {
            int colIdx = h * 8 + i;                 // == lh*4+lw for this plane slot
            uint4 w = CW[colIdx];
            int b00 = CB[colIdx];
            __half2 w00 = u2h(w.x), w01 = u2h(w.y), w10 = u2h(w.z), w11 = u2h(w.w);
            uint4 q00 = *reinterpret_cast<const uint4*>(&S_rows[b00 + zt0]);
            uint4 q01 = *reinterpret_cast<const uint4*>(&S_rows[b00 + 512 + zt0]);
            uint4 q10 = *reinterpret_cast<const uint4*>(&S_rows[b00 + 1536 + zt0]);
            uint4 q11 = *reinterpret_cast<const uint4*>(&S_rows[b00 + 2048 + zt0]);
            uint4 o;
            o.x = h2u(__hadd2(__hfma2(w01, u2h(q01.x), __hmul2(w00, u2h(q00.x))),
                              __hfma2(w11, u2h(q11.x), __hmul2(w10, u2h(q10.x)))));
            o.y = h2u(__hadd2(__hfma2(w01, u2h(q01.y), __hmul2(w00, u2h(q00.y))),
                              __hfma2(w11, u2h(q11.y), __hmul2(w10, u2h(q10.y)))));
            o.z = h2u(__hadd2(__hfma2(w01, u2h(q01.z), __hmul2(w00, u2h(q00.z))),
                              __hfma2(w11, u2h(q11.z), __hmul2(w10, u2h(q10.z)))));
            o.w = h2u(__hadd2(__hfma2(w01, u2h(q01.w), __hmul2(w00, u2h(q00.w))),
                              __hfma2(w11, u2h(q11.w), __hmul2(w10, u2h(q10.w)))));
            *reinterpret_cast<uint4*>(&S_plane[i * ROWE + zt0]) = o;
        }
        __syncthreads();

        // ---- phase 3: gather (4 LDS.64 per voxel) + z/t interp in f32 ----
        #pragma unroll
        for (int k = 0; k < 4; k++) {
            int v  = k * 256 + tid;
            int gd = v & (GD - 1);
            int c8 = v >> 7;                        // 0..7 plane slot
            int lh = h * 2 + (c8 >> 2);
            int lw = c8 & 3;
            int gh = gh0 + lh, gw = gw0 + lw;

            float zc = fminf((float)gd * sx, 31.0f);
            float z0f = floorf(zc); float fz = zc - z0f;
            int z0 = (int)z0f;
            int z1 = min(z0 + 1, D - 1);

            float g = gm[(gh * GWD + gw) * GD + gd];
            float t = fminf(fmaxf(g * 15.0f, 0.0f), 15.0f);
            float t0f = floorf(t); float ft = t - t0f;
            int t0 = (int)t0f;
            int t1 = min(t0 + 1, UP - 1);

            const uint2* P = S_plane + c8 * ROWE;
            uint2 e00 = P[z0 * 16 + t0];
            uint2 e01 = P[z0 * 16 + t1];
            uint2 e10 = P[z1 * 16 + t0];
            uint2 e11 = P[z1 * 16 + t1];

            float w00 = (1.f - fz) * (1.f - ft);
            float w01 = (1.f - fz) * ft;
            float w10 = fz * (1.f - ft);
            float w11 = fz * ft;

            float2 a01 = __half22float2(u2h(e00.x));
            float2 a23 = __half22float2(u2h(e00.y));
            float acc0 = a01.x * w00, acc1 = a01.y * w00;
            float acc2 = a23.x * w00, acc3 = a23.y * w00;

            a01 = __half22float2(u2h(e01.x)); a23 = __half22float2(u2h(e01.y));
            acc0 = fmaf(a01.x, w01, acc0); acc1 = fmaf(a01.y, w01, acc1);
            acc2 = fmaf(a23.x, w01, acc2); acc3 = fmaf(a23.y, w01, acc3);

            a01 = __half22float2(u2h(e10.x)); a23 = __half22float2(u2h(e10.y));
            acc0 = fmaf(a01.x, w10, acc0); acc1 = fmaf(a01.y, w10, acc1);
            acc2 = fmaf(a23.x, w10, acc2); acc3 = fmaf(a23.y, w10, acc3);

            a01 = __half22float2(u2h(e11.x)); a23 = __half22float2(u2h(e11.y));
            acc0 = fmaf(a01.x, w11, acc0); acc1 = fmaf(a01.y, w11, acc1);
            acc2 = fmaf(a23.x, w11, acc2); acc3 = fmaf(a23.y, w11, acc3);

            int ob = (gh * GWD + gw) * GD + gd;
            out[ob]              = acc0;
            out[ob + OUT_CH]     = acc1;
            out[ob + 2 * OUT_CH] = acc2;
            out[ob + 3 * OUT_CH] = acc3;
        }
        __syncthreads();
    }
}

extern "C" void kernel_launch(void* const* d_in, const int* in_sizes, int n_in,
                              void* d_out, int out_size)
{
    const float* bg = (const float*)d_in[0];
    const float* gm = (const float*)d_in[1];
    float* out = (float*)d_out;

    cudaFuncSetAttribute(bgrid_slice_kernel,
                         cudaFuncAttributeMaxDynamicSharedMemorySize, SMEM_BYTES);

    dim3 grid(GWD / TW, GH / TH);   // 32 x 32 = 1024 blocks
    bgrid_slice_kernel<<<grid, 256, SMEM_BYTES>>>(bg, gm, out);
}

// round 4
// speedup vs baseline: 2.2857x; 1.3898x over previous
#include <cuda_runtime.h>
#include <cuda_fp16.h>

// bg: (1, 4, 32, 32, 32, 16) f32   -> d_in[0]
// gm: (1, 1, 128, 128, 128) f32    -> d_in[1]
// out:(1, 4, 128, 128, 128) f32

#define GH 128
#define GWD 128
#define GD 128
#define H 32
#define W 32
#define D 32
#define UP 16
#define TH 4
#define TW 4
#define ROWE 512                       // [z][t] entries per (x,y) row / per column plane
#define PLANE_E (16 * ROWE)            // 16 columns
#define PLANE_BYTES (PLANE_E * 8)      // 65536

#define CH_STRIDE (H*W*D*UP)           // 524288
#define OUT_CH (GH*GWD*GD)             // 2097152

__device__ __forceinline__ __half2 u2h(unsigned int u) {
    __half2 h; *reinterpret_cast<unsigned int*>(&h) = u; return h;
}
__device__ __forceinline__ unsigned int h2u(__half2 h) {
    return *reinterpret_cast<unsigned int*>(&h);
}

__global__ void __launch_bounds__(256, 3)
bgrid_slice_kernel(const float* __restrict__ bg,
                   const float* __restrict__ gm,
                   float* __restrict__ out)
{
    extern __shared__ uint2 S_plane[];           // [col][z][t] fp16x4
    __shared__ uint4 WX3[4];                      // 3-tap x weights per lh (half2, padded)
    __shared__ uint4 WY3[4];                      // 3-tap y weights per lw

    const float sx = 31.0f / 127.0f;
    const int gh0 = blockIdx.y * TH;
    const int gw0 = blockIdx.x * TW;
    const int X = (int)floorf((float)gh0 * sx);
    const int Y = (int)floorf((float)gw0 * sx);
    const int tid = threadIdx.x;

    // ---- tiny weight tables (3-tap padded, branch-free downstream) ----
    if (tid < 8) {
        int l = tid & 3;
        int base = (tid < 4) ? gh0 : gw0;
        int O = (tid < 4) ? X : Y;
        float c = fminf((float)(base + l) * sx, 31.0f);
        float c0f = floorf(c);
        float f = c - c0f;
        int l0 = (int)c0f - O;                    // 0 or 1
        uint4 w3;
        if (l0 == 0) {
            w3.x = h2u(__float2half2_rn(1.f - f));
            w3.y = h2u(__float2half2_rn(f));
            w3.z = 0u;
        } else {
            w3.x = 0u;
            w3.y = h2u(__float2half2_rn(1.f - f));
            w3.z = h2u(__float2half2_rn(f));
        }
        w3.w = 0u;
        if (tid < 4) WX3[l] = w3; else WY3[l] = w3;
    }
    __syncthreads();

    // ---- phase 1: load 9 corner rows from global at this thread's zt, blend
    //      into 16 column planes (all in registers; only STS to plane) ----
    int rowbase[9];
    #pragma unroll
    for (int r = 0; r < 9; r++) {
        int a = r / 3, b = r - a * 3;
        int gx = min(X + a, H - 1);
        int gy = min(Y + b, W - 1);
        rowbase[r] = (gx * W + gy) * ROWE;
    }

    #pragma unroll
    for (int k = 0; k < 2; k++) {
        const int zt = k * 256 + tid;

        // load 9 rows x 4 channels, pack to fp16x4
        uint2 R[9];
        #pragma unroll
        for (int r = 0; r < 9; r++) {
            int idx = rowbase[r] + zt;
            float f0 = bg[idx];
            float f1 = bg[idx + CH_STRIDE];
            float f2 = bg[idx + 2 * CH_STRIDE];
            float f3 = bg[idx + 3 * CH_STRIDE];
            R[r].x = h2u(__floats2half2_rn(f0, f1));
            R[r].y = h2u(__floats2half2_rn(f2, f3));
        }

        // stage A: y-blend -> T[a][lw]  (3 x-rows x 4 columns)
        uint2 T[12];
        #pragma unroll
        for (int lw = 0; lw < 4; lw++) {
            uint4 wy = WY3[lw];
            __half2 w0 = u2h(wy.x), w1 = u2h(wy.y), w2 = u2h(wy.z);
            #pragma unroll
            for (int a = 0; a < 3; a++) {
                __half2 t01 = __hmul2(w0, u2h(R[a*3 + 0].x));
                t01 = __hfma2(w1, u2h(R[a*3 + 1].x), t01);
                t01 = __hfma2(w2, u2h(R[a*3 + 2].x), t01);
                __half2 t23 = __hmul2(w0, u2h(R[a*3 + 0].y));
                t23 = __hfma2(w1, u2h(R[a*3 + 1].y), t23);
                t23 = __hfma2(w2, u2h(R[a*3 + 2].y), t23);
                T[a*4 + lw].x = h2u(t01);
                T[a*4 + lw].y = h2u(t23);
            }
        }

        // stage B: x-blend -> 16 planes, write to shared
        #pragma unroll
        for (int lh = 0; lh < 4; lh++) {
            uint4 wx = WX3[lh];
            __half2 w0 = u2h(wx.x), w1 = u2h(wx.y), w2 = u2h(wx.z);
            #pragma unroll
            for (int lw = 0; lw < 4; lw++) {
                __half2 o01 = __hmul2(w0, u2h(T[0*4 + lw].x));
                o01 = __hfma2(w1, u2h(T[1*4 + lw].x), o01);
                o01 = __hfma2(w2, u2h(T[2*4 + lw].x), o01);
                __half2 o23 = __hmul2(w0, u2h(T[0*4 + lw].y));
                o23 = __hfma2(w1, u2h(T[1*4 + lw].y), o23);
                o23 = __hfma2(w2, u2h(T[2*4 + lw].y), o23);
                uint2 o; o.x = h2u(o01); o.y = h2u(o23);
                S_plane[(lh*4 + lw) * ROWE + zt] = o;
            }
        }
    }
    __syncthreads();

    // ---- phase 2: gather (4 LDS.64 per voxel) + z/t interp in f32 ----
    #pragma unroll
    for (int k = 0; k < 8; k++) {
        int v  = k * 256 + tid;
        int gd = v & (GD - 1);
        int c16 = v >> 7;                        // 0..15 (uniform per warp)
        int lh = c16 >> 2;
        int lw = c16 & 3;
        int gh = gh0 + lh, gw = gw0 + lw;

        float zc = fminf((float)gd * sx, 31.0f);
        float z0f = floorf(zc); float fz = zc - z0f;
        int z0 = (int)z0f;
        int z1 = min(z0 + 1, D - 1);

        float g = gm[(gh * GWD + gw) * GD + gd];
        float t = fminf(fmaxf(g * 15.0f, 0.0f), 15.0f);
        float t0f = floorf(t); float ft = t - t0f;
        int t0 = (int)t0f;
        int t1 = min(t0 + 1, UP - 1);

        const uint2* P = S_plane + c16 * ROWE;
        uint2 e00 = P[z0 * 16 + t0];
        uint2 e01 = P[z0 * 16 + t1];
        uint2 e10 = P[z1 * 16 + t0];
        uint2 e11 = P[z1 * 16 + t1];

        float w00 = (1.f - fz) * (1.f - ft);
        float w01 = (1.f - fz) * ft;
        float w10 = fz * (1.f - ft);
        float w11 = fz * ft;

        float2 a01 = __half22float2(u2h(e00.x));
        float2 a23 = __half22float2(u2h(e00.y));
        float acc0 = a01.x * w00, acc1 = a01.y * w00;
        float acc2 = a23.x * w00, acc3 = a23.y * w00;

        a01 = __half22float2(u2h(e01.x)); a23 = __half22float2(u2h(e01.y));
        acc0 = fmaf(a01.x, w01, acc0); acc1 = fmaf(a01.y, w01, acc1);
        acc2 = fmaf(a23.x, w01, acc2); acc3 = fmaf(a23.y, w01, acc3);

        a01 = __half22float2(u2h(e10.x)); a23 = __half22float2(u2h(e10.y));
        acc0 = fmaf(a01.x, w10, acc0); acc1 = fmaf(a01.y, w10, acc1);
        acc2 = fmaf(a23.x, w10, acc2); acc3 = fmaf(a23.y, w10, acc3);

        a01 = __half22float2(u2h(e11.x)); a23 = __half22float2(u2h(e11.y));
        acc0 = fmaf(a01.x, w11, acc0); acc1 = fmaf(a01.y, w11, acc1);
        acc2 = fmaf(a23.x, w11, acc2); acc3 = fmaf(a23.y, w11, acc3);

        int ob = (gh * GWD + gw) * GD + gd;
        out[ob]              = acc0;
        out[ob + OUT_CH]     = acc1;
        out[ob + 2 * OUT_CH] = acc2;
        out[ob + 3 * OUT_CH] = acc3;
    }
}

extern "C" void kernel_launch(void* const* d_in, const int* in_sizes, int n_in,
                              void* d_out, int out_size)
{
    const float* bg = (const float*)d_in[0];
    const float* gm = (const float*)d_in[1];
    float* out = (float*)d_out;

    cudaFuncSetAttribute(bgrid_slice_kernel,
                         cudaFuncAttributeMaxDynamicSharedMemorySize, PLANE_BYTES);

    dim3 grid(GWD / TW, GH / TH);   // 32 x 32 = 1024 blocks
    bgrid_slice_kernel<<<grid, 256, PLANE_BYTES>>>(bg, gm, out);
}